// round 1
// baseline (speedup 1.0000x reference)
#include <cuda_runtime.h>
#include <cuda_bf16.h>
#include <math.h>

// Problem constants
#define B_  4
#define T_  2048
#define C_  1024
#define H_  16
#define HD_ 64
#define M_  (B_*T_)          // 8192 rows

// Scratch (static device globals -- allocation-free per harness rules)
__device__ float g_qkv[(size_t)M_ * 3 * C_];   // [8192][3072] : q|k|v
__device__ float g_y  [(size_t)M_ * C_];       // [8192][1024] : attn output

// ---------------------------------------------------------------------------
// GEMM: C[M,N] = A[M,K] * B[N,K]^T   (A row-major MxK, B row-major NxK)
// 128x128x16 tile, 256 threads, each thread a 8x8 micro-tile as 2x2 blocks of 4
// ---------------------------------------------------------------------------
__global__ void __launch_bounds__(256) sgemm_nt_kernel(
    const float* __restrict__ A, const float* __restrict__ B,
    float* __restrict__ C, int M, int N, int K)
{
    const int BM = 128, BN = 128, BK = 16;
    __shared__ float As[BK][BM + 4];   // [k][m], padded
    __shared__ float Bs[BK][BN + 4];   // [k][n], padded

    const int tid = threadIdx.x;
    const int tx  = tid & 15;          // 0..15 (col group)
    const int ty  = tid >> 4;          // 0..15 (row group)
    const size_t brow = (size_t)blockIdx.y * BM;
    const size_t bcol = (size_t)blockIdx.x * BN;
    const float* Ag = A + brow * K;
    const float* Bg = B + bcol * K;

    float acc[8][8];
    #pragma unroll
    for (int i = 0; i < 8; i++)
        #pragma unroll
        for (int j = 0; j < 8; j++) acc[i][j] = 0.0f;

    for (int k0 = 0; k0 < K; k0 += BK) {
        // Load tiles: 128x16 floats each = 512 float4; 2 per thread per matrix
        #pragma unroll
        for (int it = 0; it < 2; it++) {
            int idx = tid + it * 256;      // 0..511
            int r   = idx >> 2;            // 0..127
            int kq  = (idx & 3) << 2;      // 0,4,8,12
            float4 va = *(const float4*)(Ag + (size_t)r * K + k0 + kq);
            As[kq+0][r] = va.x; As[kq+1][r] = va.y;
            As[kq+2][r] = va.z; As[kq+3][r] = va.w;
            float4 vb = *(const float4*)(Bg + (size_t)r * K + k0 + kq);
            Bs[kq+0][r] = vb.x; Bs[kq+1][r] = vb.y;
            Bs[kq+2][r] = vb.z; Bs[kq+3][r] = vb.w;
        }
        __syncthreads();

        #pragma unroll
        for (int k = 0; k < BK; k++) {
            float a[8], b[8];
            *(float4*)&a[0] = *(const float4*)&As[k][ty * 4];
            *(float4*)&a[4] = *(const float4*)&As[k][64 + ty * 4];
            *(float4*)&b[0] = *(const float4*)&Bs[k][tx * 4];
            *(float4*)&b[4] = *(const float4*)&Bs[k][64 + tx * 4];
            #pragma unroll
            for (int i = 0; i < 8; i++)
                #pragma unroll
                for (int j = 0; j < 8; j++)
                    acc[i][j] += a[i] * b[j];
        }
        __syncthreads();
    }

    // Write-back: rows {brow + ri*64 + ty*4 + i}, cols {bcol + ci*64 + tx*4 ..+3}
    #pragma unroll
    for (int ri = 0; ri < 2; ri++) {
        #pragma unroll
        for (int i = 0; i < 4; i++) {
            size_t row = brow + ri * 64 + ty * 4 + i;
            #pragma unroll
            for (int ci = 0; ci < 2; ci++) {
                float4 v;
                v.x = acc[ri*4+i][ci*4+0];
                v.y = acc[ri*4+i][ci*4+1];
                v.z = acc[ri*4+i][ci*4+2];
                v.w = acc[ri*4+i][ci*4+3];
                *(float4*)(C + row * N + bcol + ci * 64 + tx * 4) = v;
            }
        }
    }
}

// ---------------------------------------------------------------------------
// Fused RMSNorm + RoPE over q and k heads, in place on g_qkv.
// One warp per 64-element head vector. 2*B*T*H = 262144 vectors total.
// ---------------------------------------------------------------------------
__global__ void __launch_bounds__(256) rmsrope_kernel(float* __restrict__ qkv)
{
    int gv   = (blockIdx.x * blockDim.x + threadIdx.x) >> 5;  // vector id
    int lane = threadIdx.x & 31;
    // layout of gv: [m (8192)][h (16)][which (2)]
    int which = gv & 1;            // 0 = q, 1 = k
    int h     = (gv >> 1) & 15;
    int m     = gv >> 5;           // b*T + t
    int t     = m & (T_ - 1);

    float* base = qkv + (size_t)m * (3 * C_) + which * C_ + h * HD_;
    float x1 = base[lane];
    float x2 = base[lane + 32];

    // RMS norm over the 64 elements
    float ss = x1 * x1 + x2 * x2;
    #pragma unroll
    for (int off = 16; off; off >>= 1)
        ss += __shfl_xor_sync(0xffffffffu, ss, off);
    float r = rsqrtf(ss * (1.0f / 64.0f) + 1.1920929e-07f);
    x1 *= r; x2 *= r;

    // RoPE: pair (lane, lane+32), freq index = lane
    float inv_f = powf(10000.0f, -(float)lane * (1.0f / 32.0f));
    float ang   = (float)t * inv_f;
    float cf, sf;
    sincosf(ang, &sf, &cf);
    // reference rounds cos/sin to bf16 before applying (in fp32)
    float c = __bfloat162float(__float2bfloat16(cf));
    float s = __bfloat162float(__float2bfloat16(sf));

    base[lane]      =  x1 * c + x2 * s;
    base[lane + 32] = -x1 * s + x2 * c;
}

// ---------------------------------------------------------------------------
// Causal flash attention, fp32. BQ=64 queries x BKV=64 keys tiles, HD=64.
// 256 threads; thread (ty,tx) owns a 4x4 micro-tile of S and of O.
// Smem: Qs[d][m] (stride 64), KPs[d][n] stride 68 (K, later aliased as P[n][m]),
//       Vs[j][d] (stride 64).  Total 50176 bytes dynamic.
// ---------------------------------------------------------------------------
__global__ void __launch_bounds__(256) flash_kernel(
    const float* __restrict__ qkv, float* __restrict__ y)
{
    extern __shared__ float sm[];
    float* Qs  = sm;                    // 64*64
    float* KPs = sm + 64 * 64;          // 64*68
    float* Vs  = KPs + 64 * 68;         // 64*64

    const int tid = threadIdx.x;
    const int tx  = tid & 15;
    const int ty  = tid >> 4;
    const int qb  = blockIdx.x;
    const int bh  = blockIdx.y;
    const int b   = bh >> 4;
    const int h   = bh & 15;
    const int q0  = qb * 64;

    const float* qp = qkv + (size_t)b * T_ * (3 * C_) + h * HD_;
    const float* kp = qp + C_;
    const float* vp = qp + 2 * C_;

    // Load Q block transposed: Qs[d][m]
    #pragma unroll
    for (int it = 0; it < 4; it++) {
        int idx = tid + it * 256;           // 0..1023
        int m   = idx >> 4;                 // 0..63
        int d4  = (idx & 15) << 2;          // 0..60
        float4 v = *(const float4*)(qp + (size_t)(q0 + m) * (3 * C_) + d4);
        Qs[(d4+0) * 64 + m] = v.x; Qs[(d4+1) * 64 + m] = v.y;
        Qs[(d4+2) * 64 + m] = v.z; Qs[(d4+3) * 64 + m] = v.w;
    }

    float O[4][4];
    float rmax[4], rsum[4];
    #pragma unroll
    for (int i = 0; i < 4; i++) {
        rmax[i] = -1e30f; rsum[i] = 0.0f;
        #pragma unroll
        for (int j = 0; j < 4; j++) O[i][j] = 0.0f;
    }
    __syncthreads();

    for (int kb = 0; kb <= qb; kb++) {
        int k0 = kb * 64;
        // Load K (transposed) and V (row-major)
        #pragma unroll
        for (int it = 0; it < 4; it++) {
            int idx = tid + it * 256;
            int m   = idx >> 4;
            int d4  = (idx & 15) << 2;
            float4 kv = *(const float4*)(kp + (size_t)(k0 + m) * (3 * C_) + d4);
            KPs[(d4+0) * 68 + m] = kv.x; KPs[(d4+1) * 68 + m] = kv.y;
            KPs[(d4+2) * 68 + m] = kv.z; KPs[(d4+3) * 68 + m] = kv.w;
            float4 vv = *(const float4*)(vp + (size_t)(k0 + m) * (3 * C_) + d4);
            *(float4*)&Vs[m * 64 + d4] = vv;
        }
        __syncthreads();

        // S = Q K^T  (outer product over d)
        float s[4][4];
        #pragma unroll
        for (int i = 0; i < 4; i++)
            #pragma unroll
            for (int j = 0; j < 4; j++) s[i][j] = 0.0f;

        #pragma unroll 16
        for (int d = 0; d < 64; d++) {
            float a[4], bb[4];
            *(float4*)a  = *(const float4*)&Qs[d * 64 + ty * 4];
            *(float4*)bb = *(const float4*)&KPs[d * 68 + tx * 4];
            #pragma unroll
            for (int i = 0; i < 4; i++)
                #pragma unroll
                for (int j = 0; j < 4; j++)
                    s[i][j] += a[i] * bb[j];
        }

        // scale + causal mask (only the diagonal tile is partial)
        const bool diag = (kb == qb);
        #pragma unroll
        for (int i = 0; i < 4; i++)
            #pragma unroll
            for (int j = 0; j < 4; j++) {
                float v = s[i][j] * 0.125f;
                if (diag && (tx * 4 + j) > (ty * 4 + i)) v = -1e30f;
                s[i][j] = v;
            }

        // Online softmax per query row (16-thread groups via shfl_xor <= 8)
        #pragma unroll
        for (int i = 0; i < 4; i++) {
            float mx = fmaxf(fmaxf(s[i][0], s[i][1]), fmaxf(s[i][2], s[i][3]));
            #pragma unroll
            for (int off = 8; off; off >>= 1)
                mx = fmaxf(mx, __shfl_xor_sync(0xffffffffu, mx, off));
            float nm   = fmaxf(rmax[i], mx);
            float corr = __expf(rmax[i] - nm);
            float psum = 0.0f;
            #pragma unroll
            for (int j = 0; j < 4; j++) {
                s[i][j] = __expf(s[i][j] - nm);
                psum += s[i][j];
            }
            #pragma unroll
            for (int off = 8; off; off >>= 1)
                psum += __shfl_xor_sync(0xffffffffu, psum, off);
            rsum[i] = rsum[i] * corr + psum;
            rmax[i] = nm;
            #pragma unroll
            for (int j = 0; j < 4; j++) O[i][j] *= corr;
        }

        __syncthreads();   // everyone done reading KPs as K
        // Store P transposed into KPs: P[n][m]
        #pragma unroll
        for (int i = 0; i < 4; i++)
            #pragma unroll
            for (int j = 0; j < 4; j++)
                KPs[(tx * 4 + j) * 68 + (ty * 4 + i)] = s[i][j];
        __syncthreads();

        // O += P V  (outer product over j keys)
        #pragma unroll 16
        for (int j = 0; j < 64; j++) {
            float pa[4], vb[4];
            *(float4*)pa = *(const float4*)&KPs[j * 68 + ty * 4];
            *(float4*)vb = *(const float4*)&Vs[j * 64 + tx * 4];
            #pragma unroll
            for (int i = 0; i < 4; i++)
                #pragma unroll
                for (int jj = 0; jj < 4; jj++)
                    O[i][jj] += pa[i] * vb[jj];
        }
        __syncthreads();   // before next tile overwrites KPs/Vs
    }

    // Epilogue: O / rowsum -> y[b, t, h*64 + d]
    #pragma unroll
    for (int i = 0; i < 4; i++) {
        float inv = 1.0f / rsum[i];
        int m = q0 + ty * 4 + i;
        float4 o;
        o.x = O[i][0] * inv; o.y = O[i][1] * inv;
        o.z = O[i][2] * inv; o.w = O[i][3] * inv;
        *(float4*)&y[((size_t)b * T_ + m) * C_ + h * HD_ + tx * 4] = o;
    }
}

// ---------------------------------------------------------------------------
// Launch
// ---------------------------------------------------------------------------
extern "C" void kernel_launch(void* const* d_in, const int* in_sizes, int n_in,
                              void* d_out, int out_size)
{
    const float* x      = (const float*)d_in[0];
    const float* w_attn = (const float*)d_in[1];
    const float* w_proj = (const float*)d_in[2];
    float* out = (float*)d_out;

    float *qkv = nullptr, *y = nullptr;
    cudaGetSymbolAddress((void**)&qkv, g_qkv);
    cudaGetSymbolAddress((void**)&y,   g_y);

    // 1) qkv = x @ w_attn^T   (8192 x 3072 x 1024)
    {
        dim3 grid(3 * C_ / 128, M_ / 128);
        sgemm_nt_kernel<<<grid, 256>>>(x, w_attn, qkv, M_, 3 * C_, C_);
    }

    // 2) RMSNorm + RoPE on q,k (in place)
    {
        int vectors = 2 * M_ * H_;              // 262144
        rmsrope_kernel<<<vectors / 8, 256>>>(qkv);
    }

    // 3) Flash attention -> y
    {
        const int smem = (64 * 64 + 64 * 68 + 64 * 64) * 4;   // 50176 B
        cudaFuncSetAttribute(flash_kernel,
                             cudaFuncAttributeMaxDynamicSharedMemorySize, smem);
        dim3 grid(T_ / 64, B_ * H_);
        flash_kernel<<<grid, 256, smem>>>(qkv, y);
    }

    // 4) out = y @ w_proj^T   (8192 x 1024 x 1024)
    {
        dim3 grid(C_ / 128, M_ / 128);
        sgemm_nt_kernel<<<grid, 256>>>(y, w_proj, out, M_, C_, C_);
    }
}

// round 3
// speedup vs baseline: 1.2761x; 1.2761x over previous
#include <cuda_runtime.h>
#include <cuda_bf16.h>
#include <math.h>
#include <stdint.h>

// Problem constants
#define B_  4
#define T_  2048
#define C_  1024
#define H_  16
#define HD_ 64
#define M_  (B_*T_)          // 8192 rows

// Scratch (static device globals -- allocation-free per harness rules)
__device__ float g_qkv[(size_t)M_ * 3 * C_];   // [8192][3072] : q|k|v
__device__ float g_y  [(size_t)M_ * C_];       // [8192][1024] : attn output

// ---------------------------------------------------------------------------
// helpers
// ---------------------------------------------------------------------------
__device__ __forceinline__ uint32_t smem_u32(const void* p) {
    uint32_t a;
    asm("{ .reg .u64 t; cvta.to.shared.u64 t, %1; cvt.u32.u64 %0, t; }"
        : "=r"(a) : "l"(p));
    return a;
}

__device__ __forceinline__ void ldsm_x4(uint32_t* r, uint32_t addr) {
    asm volatile("ldmatrix.sync.aligned.m8n8.x4.shared.b16 {%0,%1,%2,%3}, [%4];"
                 : "=r"(r[0]), "=r"(r[1]), "=r"(r[2]), "=r"(r[3]) : "r"(addr));
}
__device__ __forceinline__ void ldsm_x2(uint32_t* r, uint32_t addr) {
    asm volatile("ldmatrix.sync.aligned.m8n8.x2.shared.b16 {%0,%1}, [%2];"
                 : "=r"(r[0]), "=r"(r[1]) : "r"(addr));
}
__device__ __forceinline__ void mma16816(float* d, const uint32_t* a, const uint32_t* b) {
    asm volatile(
        "mma.sync.aligned.m16n8k16.row.col.f32.bf16.bf16.f32 "
        "{%0,%1,%2,%3}, {%4,%5,%6,%7}, {%8,%9}, {%0,%1,%2,%3};"
        : "+f"(d[0]), "+f"(d[1]), "+f"(d[2]), "+f"(d[3])
        : "r"(a[0]), "r"(a[1]), "r"(a[2]), "r"(a[3]), "r"(b[0]), "r"(b[1]));
}

// split fp32 pair into bf16 hi pair + bf16 lo pair (packed, memory order)
__device__ __forceinline__ void split2(float x, float y, uint32_t& hi, uint32_t& lo) {
    __nv_bfloat16 hx = __float2bfloat16(x);
    __nv_bfloat16 hy = __float2bfloat16(y);
    float fx = __bfloat162float(hx), fy = __bfloat162float(hy);
    __nv_bfloat16 lx = __float2bfloat16(x - fx);
    __nv_bfloat16 ly = __float2bfloat16(y - fy);
    uint16_t uhx = *(uint16_t*)&hx, uhy = *(uint16_t*)&hy;
    uint16_t ulx = *(uint16_t*)&lx, uly = *(uint16_t*)&ly;
    hi = ((uint32_t)uhy << 16) | uhx;
    lo = ((uint32_t)uly << 16) | ulx;
}

// ---------------------------------------------------------------------------
// bf16x3 warp-MMA GEMM: C[M,N] = A[M,K] * B[N,K]^T  (fp32 in/out)
// CTA 128x128, K-block 32, 8 warps (2x4), warp tile 64x32, m16n8k16 MMA.
// Smem stage (32KB): Ahi 8K | Alo 8K | Bhi 8K | Blo 8K, double buffered.
// Chunk swizzle: 16B chunk c of row r stored at c ^ ((r>>1)&3)  -> ldmatrix
// conflict-free.
// ---------------------------------------------------------------------------
#define GBM 128
#define GBN 128
#define GKB 32

__global__ void __launch_bounds__(256) mma_gemm_nt(
    const float* __restrict__ A, const float* __restrict__ B,
    float* __restrict__ C, int M, int N, int K)
{
    extern __shared__ char smc[];
    const uint32_t smb = smem_u32(smc);
    const int tid  = threadIdx.x;
    const int lane = tid & 31;
    const int wid  = tid >> 5;
    const int m0w  = (wid >> 2) * 64;    // 0 or 64
    const int n0w  = (wid & 3) * 32;     // 0,32,64,96

    const size_t brow = (size_t)blockIdx.y * GBM;
    const size_t bcol = (size_t)blockIdx.x * GBN;
    const float* Ag = A + brow * K;
    const float* Bg = B + bcol * K;

    float acc[4][4][4];
    #pragma unroll
    for (int mt = 0; mt < 4; mt++)
        #pragma unroll
        for (int nt = 0; nt < 4; nt++)
            #pragma unroll
            for (int q = 0; q < 4; q++) acc[mt][nt][q] = 0.0f;

    // staged global data: 4 tasks x 8 floats
    float4 sg[4][2];

    // task decode: t in [0,1024): mat = t>>9 (0=A,1=B), r = (t&511)>>2, c = t&3
    auto issue_loads = [&](int k0) {
        #pragma unroll
        for (int i = 0; i < 4; i++) {
            int t   = tid + i * 256;
            int idx = t & 511;
            int r   = idx >> 2;
            int c   = idx & 3;
            const float* g = ((t >> 9) ? Bg : Ag) + (size_t)r * K + k0 + c * 8;
            sg[i][0] = *(const float4*)g;
            sg[i][1] = *(const float4*)(g + 4);
        }
    };
    auto store_stage = [&](int buf) {
        #pragma unroll
        for (int i = 0; i < 4; i++) {
            int t   = tid + i * 256;
            int mat = t >> 9;
            int idx = t & 511;
            int r   = idx >> 2;
            int c   = idx & 3;
            uint4 hv, lv;
            split2(sg[i][0].x, sg[i][0].y, hv.x, lv.x);
            split2(sg[i][0].z, sg[i][0].w, hv.y, lv.y);
            split2(sg[i][1].x, sg[i][1].y, hv.z, lv.z);
            split2(sg[i][1].z, sg[i][1].w, hv.w, lv.w);
            uint32_t off = (uint32_t)buf * 32768 + (uint32_t)mat * 16384
                         + (uint32_t)r * 64 + (uint32_t)((c ^ ((r >> 1) & 3)) << 4);
            *(uint4*)(smc + off)        = hv;
            *(uint4*)(smc + off + 8192) = lv;
        }
    };

    // prologue: stage 0
    issue_loads(0);
    store_stage(0);
    __syncthreads();

    const int NKB = K / GKB;
    for (int kb = 0; kb < NKB; kb++) {
        const int buf = kb & 1;
        if (kb + 1 < NKB) issue_loads((kb + 1) * GKB);

        const uint32_t base = smb + (uint32_t)buf * 32768;
        #pragma unroll
        for (int ks = 0; ks < 2; ks++) {
            uint32_t Ahi[4][4], Alo[4][4];
            #pragma unroll
            for (int mt = 0; mt < 4; mt++) {
                int r  = m0w + mt * 16 + (lane & 15);
                int ch = 2 * ks + (lane >> 4);
                uint32_t off = (uint32_t)r * 64 + (uint32_t)((ch ^ ((r >> 1) & 3)) << 4);
                ldsm_x4(Ahi[mt], base + off);
                ldsm_x4(Alo[mt], base + 8192 + off);
            }
            #pragma unroll
            for (int nt = 0; nt < 4; nt++) {
                int r  = n0w + nt * 8 + (lane & 7);
                int ch = 2 * ks + ((lane >> 3) & 1);
                uint32_t off = (uint32_t)r * 64 + (uint32_t)((ch ^ ((r >> 1) & 3)) << 4);
                uint32_t Bhi[2], Blo[2];
                ldsm_x2(Bhi, base + 16384 + off);
                ldsm_x2(Blo, base + 24576 + off);
                #pragma unroll
                for (int mt = 0; mt < 4; mt++) {
                    mma16816(acc[mt][nt], Ahi[mt], Bhi);
                    mma16816(acc[mt][nt], Ahi[mt], Blo);
                    mma16816(acc[mt][nt], Alo[mt], Bhi);
                }
            }
        }
        __syncthreads();
        if (kb + 1 < NKB) {
            store_stage((kb + 1) & 1);
            __syncthreads();
        }
    }

    // epilogue: direct global stores (fp32)
    #pragma unroll
    for (int mt = 0; mt < 4; mt++) {
        int row0 = m0w + mt * 16 + (lane >> 2);
        #pragma unroll
        for (int nt = 0; nt < 4; nt++) {
            int col = n0w + nt * 8 + (lane & 3) * 2;
            float* p = C + (brow + row0) * N + bcol + col;
            float2 v0 = make_float2(acc[mt][nt][0], acc[mt][nt][1]);
            float2 v1 = make_float2(acc[mt][nt][2], acc[mt][nt][3]);
            *(float2*)p           = v0;
            *(float2*)(p + 8 * N) = v1;
        }
    }
}

// ---------------------------------------------------------------------------
// Fused RMSNorm + RoPE over q and k heads, in place on g_qkv.
// One warp per 64-element head vector. 2*B*T*H = 262144 vectors total.
// ---------------------------------------------------------------------------
__global__ void __launch_bounds__(256) rmsrope_kernel(float* __restrict__ qkv)
{
    int gv   = (blockIdx.x * blockDim.x + threadIdx.x) >> 5;  // vector id
    int lane = threadIdx.x & 31;
    int which = gv & 1;            // 0 = q, 1 = k
    int h     = (gv >> 1) & 15;
    int m     = gv >> 5;           // b*T + t
    int t     = m & (T_ - 1);

    float* base = qkv + (size_t)m * (3 * C_) + which * C_ + h * HD_;
    float x1 = base[lane];
    float x2 = base[lane + 32];

    float ss = x1 * x1 + x2 * x2;
    #pragma unroll
    for (int off = 16; off; off >>= 1)
        ss += __shfl_xor_sync(0xffffffffu, ss, off);
    float r = rsqrtf(ss * (1.0f / 64.0f) + 1.1920929e-07f);
    x1 *= r; x2 *= r;

    float inv_f = powf(10000.0f, -(float)lane * (1.0f / 32.0f));
    float ang   = (float)t * inv_f;
    float cf, sf;
    sincosf(ang, &sf, &cf);
    float c = __bfloat162float(__float2bfloat16(cf));
    float s = __bfloat162float(__float2bfloat16(sf));

    base[lane]      =  x1 * c + x2 * s;
    base[lane + 32] = -x1 * s + x2 * c;
}

// ---------------------------------------------------------------------------
// Causal flash attention, fp32 (unchanged; known good).
// ---------------------------------------------------------------------------
__global__ void __launch_bounds__(256) flash_kernel(
    const float* __restrict__ qkv, float* __restrict__ y)
{
    extern __shared__ float smf[];
    float* Qs  = smf;                   // 64*64
    float* KPs = smf + 64 * 64;         // 64*68
    float* Vs  = KPs + 64 * 68;         // 64*64

    const int tid = threadIdx.x;
    const int tx  = tid & 15;
    const int ty  = tid >> 4;
    const int qb  = blockIdx.x;
    const int bh  = blockIdx.y;
    const int b   = bh >> 4;
    const int h   = bh & 15;
    const int q0  = qb * 64;

    const float* qp = qkv + (size_t)b * T_ * (3 * C_) + h * HD_;
    const float* kp = qp + C_;
    const float* vp = qp + 2 * C_;

    #pragma unroll
    for (int it = 0; it < 4; it++) {
        int idx = tid + it * 256;
        int m   = idx >> 4;
        int d4  = (idx & 15) << 2;
        float4 v = *(const float4*)(qp + (size_t)(q0 + m) * (3 * C_) + d4);
        Qs[(d4+0) * 64 + m] = v.x; Qs[(d4+1) * 64 + m] = v.y;
        Qs[(d4+2) * 64 + m] = v.z; Qs[(d4+3) * 64 + m] = v.w;
    }

    float O[4][4];
    float rmax[4], rsum[4];
    #pragma unroll
    for (int i = 0; i < 4; i++) {
        rmax[i] = -1e30f; rsum[i] = 0.0f;
        #pragma unroll
        for (int j = 0; j < 4; j++) O[i][j] = 0.0f;
    }
    __syncthreads();

    for (int kb = 0; kb <= qb; kb++) {
        int k0 = kb * 64;
        #pragma unroll
        for (int it = 0; it < 4; it++) {
            int idx = tid + it * 256;
            int m   = idx >> 4;
            int d4  = (idx & 15) << 2;
            float4 kv = *(const float4*)(kp + (size_t)(k0 + m) * (3 * C_) + d4);
            KPs[(d4+0) * 68 + m] = kv.x; KPs[(d4+1) * 68 + m] = kv.y;
            KPs[(d4+2) * 68 + m] = kv.z; KPs[(d4+3) * 68 + m] = kv.w;
            float4 vv = *(const float4*)(vp + (size_t)(k0 + m) * (3 * C_) + d4);
            *(float4*)&Vs[m * 64 + d4] = vv;
        }
        __syncthreads();

        float s[4][4];
        #pragma unroll
        for (int i = 0; i < 4; i++)
            #pragma unroll
            for (int j = 0; j < 4; j++) s[i][j] = 0.0f;

        #pragma unroll 16
        for (int d = 0; d < 64; d++) {
            float a[4], bb[4];
            *(float4*)a  = *(const float4*)&Qs[d * 64 + ty * 4];
            *(float4*)bb = *(const float4*)&KPs[d * 68 + tx * 4];
            #pragma unroll
            for (int i = 0; i < 4; i++)
                #pragma unroll
                for (int j = 0; j < 4; j++)
                    s[i][j] += a[i] * bb[j];
        }

        const bool diag = (kb == qb);
        #pragma unroll
        for (int i = 0; i < 4; i++)
            #pragma unroll
            for (int j = 0; j < 4; j++) {
                float v = s[i][j] * 0.125f;
                if (diag && (tx * 4 + j) > (ty * 4 + i)) v = -1e30f;
                s[i][j] = v;
            }

        #pragma unroll
        for (int i = 0; i < 4; i++) {
            float mx = fmaxf(fmaxf(s[i][0], s[i][1]), fmaxf(s[i][2], s[i][3]));
            #pragma unroll
            for (int off = 8; off; off >>= 1)
                mx = fmaxf(mx, __shfl_xor_sync(0xffffffffu, mx, off));
            float nm   = fmaxf(rmax[i], mx);
            float corr = __expf(rmax[i] - nm);
            float psum = 0.0f;
            #pragma unroll
            for (int j = 0; j < 4; j++) {
                s[i][j] = __expf(s[i][j] - nm);
                psum += s[i][j];
            }
            #pragma unroll
            for (int off = 8; off; off >>= 1)
                psum += __shfl_xor_sync(0xffffffffu, psum, off);
            rsum[i] = rsum[i] * corr + psum;
            rmax[i] = nm;
            #pragma unroll
            for (int j = 0; j < 4; j++) O[i][j] *= corr;
        }

        __syncthreads();
        #pragma unroll
        for (int i = 0; i < 4; i++)
            #pragma unroll
            for (int j = 0; j < 4; j++)
                KPs[(tx * 4 + j) * 68 + (ty * 4 + i)] = s[i][j];
        __syncthreads();

        #pragma unroll 16
        for (int j = 0; j < 64; j++) {
            float pa[4], vb[4];
            *(float4*)pa = *(const float4*)&KPs[j * 68 + ty * 4];
            *(float4*)vb = *(const float4*)&Vs[j * 64 + tx * 4];
            #pragma unroll
            for (int i = 0; i < 4; i++)
                #pragma unroll
                for (int jj = 0; jj < 4; jj++)
                    O[i][jj] += pa[i] * vb[jj];
        }
        __syncthreads();
    }

    #pragma unroll
    for (int i = 0; i < 4; i++) {
        float inv = 1.0f / rsum[i];
        int m = q0 + ty * 4 + i;
        float4 o;
        o.x = O[i][0] * inv; o.y = O[i][1] * inv;
        o.z = O[i][2] * inv; o.w = O[i][3] * inv;
        *(float4*)&y[((size_t)b * T_ + m) * C_ + h * HD_ + tx * 4] = o;
    }
}

// ---------------------------------------------------------------------------
// Launch
// ---------------------------------------------------------------------------
extern "C" void kernel_launch(void* const* d_in, const int* in_sizes, int n_in,
                              void* d_out, int out_size)
{
    const float* x      = (const float*)d_in[0];
    const float* w_attn = (const float*)d_in[1];
    const float* w_proj = (const float*)d_in[2];
    float* out = (float*)d_out;

    float *qkv = nullptr, *y = nullptr;
    cudaGetSymbolAddress((void**)&qkv, g_qkv);
    cudaGetSymbolAddress((void**)&y,   g_y);

    const int gemm_smem = 65536;
    cudaFuncSetAttribute(mma_gemm_nt,
                         cudaFuncAttributeMaxDynamicSharedMemorySize, gemm_smem);

    // 1) qkv = x @ w_attn^T   (8192 x 3072 x 1024) -- bf16x3 warp MMA
    {
        dim3 grid(3 * C_ / GBN, M_ / GBM);   // 24 x 64
        mma_gemm_nt<<<grid, 256, gemm_smem>>>(x, w_attn, qkv, M_, 3 * C_, C_);
    }

    // 2) RMSNorm + RoPE on q,k (in place)
    {
        int vectors = 2 * M_ * H_;              // 262144
        rmsrope_kernel<<<vectors / 8, 256>>>(qkv);
    }

    // 3) Flash attention -> y
    {
        const int smem = (64 * 64 + 64 * 68 + 64 * 64) * 4;   // 50176 B
        cudaFuncSetAttribute(flash_kernel,
                             cudaFuncAttributeMaxDynamicSharedMemorySize, smem);
        dim3 grid(T_ / 64, B_ * H_);
        flash_kernel<<<grid, 256, smem>>>(qkv, y);
    }

    // 4) out = y @ w_proj^T   (8192 x 1024 x 1024) -- bf16x3 warp MMA
    {
        dim3 grid(C_ / GBN, M_ / GBM);       // 8 x 64
        mma_gemm_nt<<<grid, 256, gemm_smem>>>(y, w_proj, out, M_, C_, C_);
    }
}

// round 4
// speedup vs baseline: 1.9873x; 1.5572x over previous
#include <cuda_runtime.h>
#include <cuda_bf16.h>
#include <math.h>
#include <stdint.h>

// Problem constants
#define B_  4
#define T_  2048
#define C_  1024
#define H_  16
#define HD_ 64
#define M_  (B_*T_)          // 8192 rows

// Scratch (static device globals -- allocation-free per harness rules)
__device__ float g_qkv[(size_t)M_ * 3 * C_];            // fp32 q|k|v (GEMM1 out)
__device__ __nv_bfloat16 g_qkvh[(size_t)M_ * 3 * C_];   // bf16 hi (post norm/rope)
__device__ __nv_bfloat16 g_qkvl[(size_t)M_ * 3 * C_];   // bf16 lo
__device__ float g_y  [(size_t)M_ * C_];                // attn output

// ---------------------------------------------------------------------------
// helpers
// ---------------------------------------------------------------------------
__device__ __forceinline__ uint32_t smem_u32(const void* p) {
    uint32_t a;
    asm("{ .reg .u64 t; cvta.to.shared.u64 t, %1; cvt.u32.u64 %0, t; }"
        : "=r"(a) : "l"(p));
    return a;
}

__device__ __forceinline__ void ldsm_x4(uint32_t* r, uint32_t addr) {
    asm volatile("ldmatrix.sync.aligned.m8n8.x4.shared.b16 {%0,%1,%2,%3}, [%4];"
                 : "=r"(r[0]), "=r"(r[1]), "=r"(r[2]), "=r"(r[3]) : "r"(addr));
}
__device__ __forceinline__ void ldsm_x4_t(uint32_t* r, uint32_t addr) {
    asm volatile("ldmatrix.sync.aligned.m8n8.x4.trans.shared.b16 {%0,%1,%2,%3}, [%4];"
                 : "=r"(r[0]), "=r"(r[1]), "=r"(r[2]), "=r"(r[3]) : "r"(addr));
}
__device__ __forceinline__ void ldsm_x2(uint32_t* r, uint32_t addr) {
    asm volatile("ldmatrix.sync.aligned.m8n8.x2.shared.b16 {%0,%1}, [%2];"
                 : "=r"(r[0]), "=r"(r[1]) : "r"(addr));
}
__device__ __forceinline__ void mma16816(float* d, const uint32_t* a, const uint32_t* b) {
    asm volatile(
        "mma.sync.aligned.m16n8k16.row.col.f32.bf16.bf16.f32 "
        "{%0,%1,%2,%3}, {%4,%5,%6,%7}, {%8,%9}, {%0,%1,%2,%3};"
        : "+f"(d[0]), "+f"(d[1]), "+f"(d[2]), "+f"(d[3])
        : "r"(a[0]), "r"(a[1]), "r"(a[2]), "r"(a[3]), "r"(b[0]), "r"(b[1]));
}

// split fp32 pair into bf16 hi pair + bf16 lo pair (x -> low half, y -> high)
__device__ __forceinline__ void split2(float x, float y, uint32_t& hi, uint32_t& lo) {
    __nv_bfloat16 hx = __float2bfloat16(x);
    __nv_bfloat16 hy = __float2bfloat16(y);
    float fx = __bfloat162float(hx), fy = __bfloat162float(hy);
    __nv_bfloat16 lx = __float2bfloat16(x - fx);
    __nv_bfloat16 ly = __float2bfloat16(y - fy);
    uint16_t uhx = *(uint16_t*)&hx, uhy = *(uint16_t*)&hy;
    uint16_t ulx = *(uint16_t*)&lx, uly = *(uint16_t*)&ly;
    hi = ((uint32_t)uhy << 16) | uhx;
    lo = ((uint32_t)uly << 16) | ulx;
}

// ---------------------------------------------------------------------------
// bf16x3 warp-MMA GEMM: C[M,N] = A[M,K] * B[N,K]^T  (fp32 in/out) [unchanged]
// ---------------------------------------------------------------------------
#define GBM 128
#define GBN 128
#define GKB 32

__global__ void __launch_bounds__(256) mma_gemm_nt(
    const float* __restrict__ A, const float* __restrict__ B,
    float* __restrict__ C, int M, int N, int K)
{
    extern __shared__ char smc[];
    const uint32_t smb = smem_u32(smc);
    const int tid  = threadIdx.x;
    const int lane = tid & 31;
    const int wid  = tid >> 5;
    const int m0w  = (wid >> 2) * 64;
    const int n0w  = (wid & 3) * 32;

    const size_t brow = (size_t)blockIdx.y * GBM;
    const size_t bcol = (size_t)blockIdx.x * GBN;
    const float* Ag = A + brow * K;
    const float* Bg = B + bcol * K;

    float acc[4][4][4];
    #pragma unroll
    for (int mt = 0; mt < 4; mt++)
        #pragma unroll
        for (int nt = 0; nt < 4; nt++)
            #pragma unroll
            for (int q = 0; q < 4; q++) acc[mt][nt][q] = 0.0f;

    float4 sg[4][2];

    auto issue_loads = [&](int k0) {
        #pragma unroll
        for (int i = 0; i < 4; i++) {
            int t   = tid + i * 256;
            int idx = t & 511;
            int r   = idx >> 2;
            int c   = idx & 3;
            const float* g = ((t >> 9) ? Bg : Ag) + (size_t)r * K + k0 + c * 8;
            sg[i][0] = *(const float4*)g;
            sg[i][1] = *(const float4*)(g + 4);
        }
    };
    auto store_stage = [&](int buf) {
        #pragma unroll
        for (int i = 0; i < 4; i++) {
            int t   = tid + i * 256;
            int mat = t >> 9;
            int idx = t & 511;
            int r   = idx >> 2;
            int c   = idx & 3;
            uint4 hv, lv;
            split2(sg[i][0].x, sg[i][0].y, hv.x, lv.x);
            split2(sg[i][0].z, sg[i][0].w, hv.y, lv.y);
            split2(sg[i][1].x, sg[i][1].y, hv.z, lv.z);
            split2(sg[i][1].z, sg[i][1].w, hv.w, lv.w);
            uint32_t off = (uint32_t)buf * 32768 + (uint32_t)mat * 16384
                         + (uint32_t)r * 64 + (uint32_t)((c ^ ((r >> 1) & 3)) << 4);
            *(uint4*)(smc + off)        = hv;
            *(uint4*)(smc + off + 8192) = lv;
        }
    };

    issue_loads(0);
    store_stage(0);
    __syncthreads();

    const int NKB = K / GKB;
    for (int kb = 0; kb < NKB; kb++) {
        const int buf = kb & 1;
        if (kb + 1 < NKB) issue_loads((kb + 1) * GKB);

        const uint32_t base = smb + (uint32_t)buf * 32768;
        #pragma unroll
        for (int ks = 0; ks < 2; ks++) {
            uint32_t Ahi[4][4], Alo[4][4];
            #pragma unroll
            for (int mt = 0; mt < 4; mt++) {
                int r  = m0w + mt * 16 + (lane & 15);
                int ch = 2 * ks + (lane >> 4);
                uint32_t off = (uint32_t)r * 64 + (uint32_t)((ch ^ ((r >> 1) & 3)) << 4);
                ldsm_x4(Ahi[mt], base + off);
                ldsm_x4(Alo[mt], base + 8192 + off);
            }
            #pragma unroll
            for (int nt = 0; nt < 4; nt++) {
                int r  = n0w + nt * 8 + (lane & 7);
                int ch = 2 * ks + ((lane >> 3) & 1);
                uint32_t off = (uint32_t)r * 64 + (uint32_t)((ch ^ ((r >> 1) & 3)) << 4);
                uint32_t Bhi[2], Blo[2];
                ldsm_x2(Bhi, base + 16384 + off);
                ldsm_x2(Blo, base + 24576 + off);
                #pragma unroll
                for (int mt = 0; mt < 4; mt++) {
                    mma16816(acc[mt][nt], Ahi[mt], Bhi);
                    mma16816(acc[mt][nt], Ahi[mt], Blo);
                    mma16816(acc[mt][nt], Alo[mt], Bhi);
                }
            }
        }
        __syncthreads();
        if (kb + 1 < NKB) {
            store_stage((kb + 1) & 1);
            __syncthreads();
        }
    }

    #pragma unroll
    for (int mt = 0; mt < 4; mt++) {
        int row0 = m0w + mt * 16 + (lane >> 2);
        #pragma unroll
        for (int nt = 0; nt < 4; nt++) {
            int col = n0w + nt * 8 + (lane & 3) * 2;
            float* p = C + (brow + row0) * N + bcol + col;
            *(float2*)p           = make_float2(acc[mt][nt][0], acc[mt][nt][1]);
            *(float2*)(p + 8 * N) = make_float2(acc[mt][nt][2], acc[mt][nt][3]);
        }
    }
}

// ---------------------------------------------------------------------------
// RMSNorm + RoPE on q,k  ->  bf16 hi/lo arrays (no fp32 writeback)
// ---------------------------------------------------------------------------
__global__ void __launch_bounds__(256) rmsrope_split_kernel(
    const float* __restrict__ qkv,
    __nv_bfloat16* __restrict__ qh, __nv_bfloat16* __restrict__ ql)
{
    int gv   = (blockIdx.x * blockDim.x + threadIdx.x) >> 5;
    int lane = threadIdx.x & 31;
    int which = gv & 1;
    int h     = (gv >> 1) & 15;
    int m     = gv >> 5;
    int t     = m & (T_ - 1);

    size_t off = (size_t)m * (3 * C_) + which * C_ + h * HD_;
    const float* base = qkv + off;
    float x1 = base[lane];
    float x2 = base[lane + 32];

    float ss = x1 * x1 + x2 * x2;
    #pragma unroll
    for (int o = 16; o; o >>= 1)
        ss += __shfl_xor_sync(0xffffffffu, ss, o);
    float r = rsqrtf(ss * (1.0f / 64.0f) + 1.1920929e-07f);
    x1 *= r; x2 *= r;

    float inv_f = powf(10000.0f, -(float)lane * (1.0f / 32.0f));
    float ang   = (float)t * inv_f;
    float cf, sf;
    sincosf(ang, &sf, &cf);
    float c = __bfloat162float(__float2bfloat16(cf));
    float s = __bfloat162float(__float2bfloat16(sf));

    float y1 =  x1 * c + x2 * s;
    float y2 = -x1 * s + x2 * c;

    __nv_bfloat16 h1 = __float2bfloat16(y1);
    __nv_bfloat16 h2 = __float2bfloat16(y2);
    qh[off + lane]      = h1;
    qh[off + lane + 32] = h2;
    ql[off + lane]      = __float2bfloat16(y1 - __bfloat162float(h1));
    ql[off + lane + 32] = __float2bfloat16(y2 - __bfloat162float(h2));
}

// ---------------------------------------------------------------------------
// V: elementwise fp32 -> bf16 hi/lo
// ---------------------------------------------------------------------------
__global__ void __launch_bounds__(256) vsplit_kernel(
    const float* __restrict__ qkv,
    __nv_bfloat16* __restrict__ qh, __nv_bfloat16* __restrict__ ql)
{
    int idx = blockIdx.x * blockDim.x + threadIdx.x;   // over M_*C_/4 float4s
    int m   = idx >> 8;                                // C_/4 = 256
    int dq  = (idx & 255) << 2;
    size_t off = (size_t)m * (3 * C_) + 2 * C_ + dq;
    float4 v = *(const float4*)(qkv + off);
    uint32_t h01, l01, h23, l23;
    split2(v.x, v.y, h01, l01);
    split2(v.z, v.w, h23, l23);
    *(uint2*)(qh + off) = make_uint2(h01, h23);
    *(uint2*)(ql + off) = make_uint2(l01, l23);
}

// ---------------------------------------------------------------------------
// Flash attention with bf16x3 warp MMA.
// CTA: 128 queries, key tiles of 64.  8 warps x 16 query rows.
// Smem 64KB: Qhi|Qlo (32K) + Khi|Klo (16K) + Vhi|Vlo (16K), swizzle ch^=(r&7).
// ---------------------------------------------------------------------------
#define FQ_HI 0
#define FQ_LO 16384
#define FK_HI 32768
#define FK_LO 40960
#define FV_HI 49152
#define FV_LO 57344

__global__ void __launch_bounds__(256) flash_mma_kernel(
    const __nv_bfloat16* __restrict__ qh, const __nv_bfloat16* __restrict__ ql,
    float* __restrict__ y)
{
    extern __shared__ char smc[];
    const uint32_t smb = smem_u32(smc);
    const int tid  = threadIdx.x;
    const int lane = tid & 31;
    const int wid  = tid >> 5;
    const int qblk = blockIdx.x;
    const int bh   = blockIdx.y;
    const int b    = bh >> 4, h = bh & 15;
    const int q0   = qblk * 128;

    const size_t hb = (size_t)b * T_ * (3 * C_) + h * HD_;

    // Q tile copy: 128 rows x 8 chunks = 1024 tasks
    #pragma unroll
    for (int i = 0; i < 4; i++) {
        int t = tid + i * 256;
        int r = t >> 3, c = t & 7;
        size_t go = hb + (size_t)(q0 + r) * (3 * C_) + c * 8;
        uint4 hv = *(const uint4*)(qh + go);
        uint4 lv = *(const uint4*)(ql + go);
        uint32_t off = r * 128 + ((c ^ (r & 7)) << 4);
        *(uint4*)(smc + FQ_HI + off) = hv;
        *(uint4*)(smc + FQ_LO + off) = lv;
    }
    __syncthreads();

    // per-warp Q A-fragments (rows wid*16..+15), 4 k-steps over d
    uint32_t Qh[4][4], Ql[4][4];
    {
        int r = wid * 16 + (lane & 15);
        #pragma unroll
        for (int s = 0; s < 4; s++) {
            int ch = 2 * s + (lane >> 4);
            uint32_t off = r * 128 + ((ch ^ (r & 7)) << 4);
            ldsm_x4(Qh[s], smb + FQ_HI + off);
            ldsm_x4(Ql[s], smb + FQ_LO + off);
        }
    }

    float S[8][4], O[8][4];
    float rmax[2] = {-1e30f, -1e30f}, rsum[2] = {0.f, 0.f};
    #pragma unroll
    for (int j = 0; j < 8; j++)
        #pragma unroll
        for (int q = 0; q < 4; q++) O[j][q] = 0.f;

    const int row0 = q0 + wid * 16 + (lane >> 2);
    const int ktiles = 2 * qblk + 2;

    for (int kt = 0; kt < ktiles; kt++) {
        const int k0 = kt * 64;
        // K/V tile copy: 64 rows x 8 chunks = 512 tasks
        #pragma unroll
        for (int i = 0; i < 2; i++) {
            int t = tid + i * 256;
            int r = t >> 3, c = t & 7;
            size_t go = hb + (size_t)(k0 + r) * (3 * C_) + c * 8;
            uint32_t off = r * 128 + ((c ^ (r & 7)) << 4);
            uint4 kh = *(const uint4*)(qh + go + C_);
            uint4 kl = *(const uint4*)(ql + go + C_);
            *(uint4*)(smc + FK_HI + off) = kh;
            *(uint4*)(smc + FK_LO + off) = kl;
            uint4 vh = *(const uint4*)(qh + go + 2 * C_);
            uint4 vl = *(const uint4*)(ql + go + 2 * C_);
            *(uint4*)(smc + FV_HI + off) = vh;
            *(uint4*)(smc + FV_LO + off) = vl;
        }
        __syncthreads();

        // S = Q K^T (3-term bf16)
        #pragma unroll
        for (int j = 0; j < 8; j++)
            #pragma unroll
            for (int q = 0; q < 4; q++) S[j][q] = 0.f;

        #pragma unroll
        for (int jp = 0; jp < 4; jp++) {
            #pragma unroll
            for (int s = 0; s < 4; s++) {
                int r  = jp * 16 + (lane & 15);
                int ch = 2 * s + (lane >> 4);
                uint32_t off = r * 128 + ((ch ^ (r & 7)) << 4);
                uint32_t Bh[4], Bl[4];
                ldsm_x4(Bh, smb + FK_HI + off);
                ldsm_x4(Bl, smb + FK_LO + off);
                uint32_t b0h[2] = {Bh[0], Bh[2]}, b1h[2] = {Bh[1], Bh[3]};
                uint32_t b0l[2] = {Bl[0], Bl[2]}, b1l[2] = {Bl[1], Bl[3]};
                mma16816(S[2*jp],   Qh[s], b0h);
                mma16816(S[2*jp],   Ql[s], b0h);
                mma16816(S[2*jp],   Qh[s], b0l);
                mma16816(S[2*jp+1], Qh[s], b1h);
                mma16816(S[2*jp+1], Ql[s], b1h);
                mma16816(S[2*jp+1], Qh[s], b1l);
            }
        }

        // scale + causal mask (only 2 diagonal tiles are partial)
        if (kt >= 2 * qblk) {
            #pragma unroll
            for (int j = 0; j < 8; j++) {
                int colb = k0 + j * 8 + (lane & 3) * 2;
                #pragma unroll
                for (int q = 0; q < 4; q++) {
                    int key  = colb + (q & 1);
                    int grow = row0 + (q >> 1) * 8;
                    S[j][q] = (key > grow) ? -1e30f : S[j][q] * 0.125f;
                }
            }
        } else {
            #pragma unroll
            for (int j = 0; j < 8; j++)
                #pragma unroll
                for (int q = 0; q < 4; q++) S[j][q] *= 0.125f;
        }

        // online softmax (two row-halves per thread)
        #pragma unroll
        for (int hf = 0; hf < 2; hf++) {
            float mx = -1e30f;
            #pragma unroll
            for (int j = 0; j < 8; j++)
                mx = fmaxf(mx, fmaxf(S[j][2*hf], S[j][2*hf+1]));
            mx = fmaxf(mx, __shfl_xor_sync(0xffffffffu, mx, 1));
            mx = fmaxf(mx, __shfl_xor_sync(0xffffffffu, mx, 2));
            float nm   = fmaxf(rmax[hf], mx);
            float corr = __expf(rmax[hf] - nm);
            rmax[hf] = nm;
            float ps = 0.f;
            #pragma unroll
            for (int j = 0; j < 8; j++) {
                float e0 = __expf(S[j][2*hf]   - nm);
                float e1 = __expf(S[j][2*hf+1] - nm);
                S[j][2*hf] = e0; S[j][2*hf+1] = e1;
                ps += e0 + e1;
            }
            ps += __shfl_xor_sync(0xffffffffu, ps, 1);
            ps += __shfl_xor_sync(0xffffffffu, ps, 2);
            rsum[hf] = rsum[hf] * corr + ps;
            #pragma unroll
            for (int j = 0; j < 8; j++) { O[j][2*hf] *= corr; O[j][2*hf+1] *= corr; }
        }

        // O += P V : P a-frags built in registers from S accumulators
        #pragma unroll
        for (int s = 0; s < 4; s++) {
            uint32_t Ph[4], Pl[4];
            split2(S[2*s][0],   S[2*s][1],   Ph[0], Pl[0]);
            split2(S[2*s][2],   S[2*s][3],   Ph[1], Pl[1]);
            split2(S[2*s+1][0], S[2*s+1][1], Ph[2], Pl[2]);
            split2(S[2*s+1][2], S[2*s+1][3], Ph[3], Pl[3]);
            #pragma unroll
            for (int jp = 0; jp < 4; jp++) {
                int mm = lane >> 3, lr = lane & 7;
                int r  = 16 * s + lr + 8 * (mm & 1);
                int ch = 2 * jp + (mm >> 1);
                uint32_t off = r * 128 + ((ch ^ (r & 7)) << 4);
                uint32_t Bh[4], Bl[4];
                ldsm_x4_t(Bh, smb + FV_HI + off);
                ldsm_x4_t(Bl, smb + FV_LO + off);
                uint32_t b0h[2] = {Bh[0], Bh[1]}, b1h[2] = {Bh[2], Bh[3]};
                uint32_t b0l[2] = {Bl[0], Bl[1]}, b1l[2] = {Bl[2], Bl[3]};
                mma16816(O[2*jp],   Ph, b0h);
                mma16816(O[2*jp],   Pl, b0h);
                mma16816(O[2*jp],   Ph, b0l);
                mma16816(O[2*jp+1], Ph, b1h);
                mma16816(O[2*jp+1], Pl, b1h);
                mma16816(O[2*jp+1], Ph, b1l);
            }
        }
        __syncthreads();
    }

    // epilogue
    float inv0 = 1.f / rsum[0], inv1 = 1.f / rsum[1];
    #pragma unroll
    for (int j = 0; j < 8; j++) {
        int col = h * HD_ + j * 8 + (lane & 3) * 2;
        size_t base0 = ((size_t)b * T_ + row0) * C_ + col;
        *(float2*)&y[base0] = make_float2(O[j][0] * inv0, O[j][1] * inv0);
        *(float2*)&y[base0 + 8 * (size_t)C_] =
            make_float2(O[j][2] * inv1, O[j][3] * inv1);
    }
}

// ---------------------------------------------------------------------------
// Launch
// ---------------------------------------------------------------------------
extern "C" void kernel_launch(void* const* d_in, const int* in_sizes, int n_in,
                              void* d_out, int out_size)
{
    const float* x      = (const float*)d_in[0];
    const float* w_attn = (const float*)d_in[1];
    const float* w_proj = (const float*)d_in[2];
    float* out = (float*)d_out;

    float *qkv = nullptr, *y = nullptr;
    __nv_bfloat16 *qkvh = nullptr, *qkvl = nullptr;
    cudaGetSymbolAddress((void**)&qkv,  g_qkv);
    cudaGetSymbolAddress((void**)&y,    g_y);
    cudaGetSymbolAddress((void**)&qkvh, g_qkvh);
    cudaGetSymbolAddress((void**)&qkvl, g_qkvl);

    const int gemm_smem = 65536;
    cudaFuncSetAttribute(mma_gemm_nt,
                         cudaFuncAttributeMaxDynamicSharedMemorySize, gemm_smem);

    // 1) qkv = x @ w_attn^T
    {
        dim3 grid(3 * C_ / GBN, M_ / GBM);
        mma_gemm_nt<<<grid, 256, gemm_smem>>>(x, w_attn, qkv, M_, 3 * C_, C_);
    }

    // 2a) RMSNorm + RoPE on q,k -> bf16 hi/lo
    {
        int vectors = 2 * M_ * H_;              // 262144 warps
        rmsrope_split_kernel<<<vectors / 8, 256>>>(qkv, qkvh, qkvl);
    }
    // 2b) V -> bf16 hi/lo
    {
        int n4 = M_ * C_ / 4;                    // 2M float4s
        vsplit_kernel<<<n4 / 256, 256>>>(qkv, qkvh, qkvl);
    }

    // 3) Flash attention (bf16x3 MMA) -> y
    {
        const int smem = 65536;
        cudaFuncSetAttribute(flash_mma_kernel,
                             cudaFuncAttributeMaxDynamicSharedMemorySize, smem);
        dim3 grid(T_ / 128, B_ * H_);
        flash_mma_kernel<<<grid, 256, smem>>>(qkvh, qkvl, y);
    }

    // 4) out = y @ w_proj^T
    {
        dim3 grid(C_ / GBN, M_ / GBM);
        mma_gemm_nt<<<grid, 256, gemm_smem>>>(y, w_proj, out, M_, C_, C_);
    }
}

// round 5
// speedup vs baseline: 2.7490x; 1.3833x over previous
#include <cuda_runtime.h>
#include <cuda_bf16.h>
#include <math.h>
#include <stdint.h>

// Problem constants
#define B_  4
#define T_  2048
#define C_  1024
#define H_  16
#define HD_ 64
#define M_  (B_*T_)          // 8192 rows

// Scratch (static device globals -- allocation-free per harness rules)
__device__ float g_qkv[(size_t)M_ * 3 * C_];            // fp32 q|k|v (GEMM1 out)
__device__ __nv_bfloat16 g_qkvh[(size_t)M_ * 3 * C_];   // bf16 hi (post norm/rope)
__device__ __nv_bfloat16 g_qkvl[(size_t)M_ * 3 * C_];   // bf16 lo
__device__ __nv_bfloat16 g_xh[(size_t)M_ * C_], g_xl[(size_t)M_ * C_];
__device__ __nv_bfloat16 g_wah[(size_t)3 * C_ * C_], g_wal[(size_t)3 * C_ * C_];
__device__ __nv_bfloat16 g_wph[(size_t)C_ * C_],     g_wpl[(size_t)C_ * C_];
__device__ __nv_bfloat16 g_yh[(size_t)M_ * C_],      g_yl[(size_t)M_ * C_];

// ---------------------------------------------------------------------------
// helpers
// ---------------------------------------------------------------------------
__device__ __forceinline__ uint32_t smem_u32(const void* p) {
    uint32_t a;
    asm("{ .reg .u64 t; cvta.to.shared.u64 t, %1; cvt.u32.u64 %0, t; }"
        : "=r"(a) : "l"(p));
    return a;
}
__device__ __forceinline__ void cp16(uint32_t dst, const void* src) {
    asm volatile("cp.async.cg.shared.global [%0], [%1], 16;" :: "r"(dst), "l"(src));
}
__device__ __forceinline__ void cp_commit() {
    asm volatile("cp.async.commit_group;" ::: "memory");
}
template<int N> __device__ __forceinline__ void cp_wait() {
    asm volatile("cp.async.wait_group %0;" :: "n"(N) : "memory");
}

__device__ __forceinline__ void ldsm_x4(uint32_t* r, uint32_t addr) {
    asm volatile("ldmatrix.sync.aligned.m8n8.x4.shared.b16 {%0,%1,%2,%3}, [%4];"
                 : "=r"(r[0]), "=r"(r[1]), "=r"(r[2]), "=r"(r[3]) : "r"(addr));
}
__device__ __forceinline__ void ldsm_x4_t(uint32_t* r, uint32_t addr) {
    asm volatile("ldmatrix.sync.aligned.m8n8.x4.trans.shared.b16 {%0,%1,%2,%3}, [%4];"
                 : "=r"(r[0]), "=r"(r[1]), "=r"(r[2]), "=r"(r[3]) : "r"(addr));
}
__device__ __forceinline__ void ldsm_x2(uint32_t* r, uint32_t addr) {
    asm volatile("ldmatrix.sync.aligned.m8n8.x2.shared.b16 {%0,%1}, [%2];"
                 : "=r"(r[0]), "=r"(r[1]) : "r"(addr));
}
__device__ __forceinline__ void mma16816(float* d, const uint32_t* a, const uint32_t* b) {
    asm volatile(
        "mma.sync.aligned.m16n8k16.row.col.f32.bf16.bf16.f32 "
        "{%0,%1,%2,%3}, {%4,%5,%6,%7}, {%8,%9}, {%0,%1,%2,%3};"
        : "+f"(d[0]), "+f"(d[1]), "+f"(d[2]), "+f"(d[3])
        : "r"(a[0]), "r"(a[1]), "r"(a[2]), "r"(a[3]), "r"(b[0]), "r"(b[1]));
}

// split fp32 pair into bf16 hi pair + bf16 lo pair (x -> low half, y -> high)
__device__ __forceinline__ void split2(float x, float y, uint32_t& hi, uint32_t& lo) {
    __nv_bfloat16 hx = __float2bfloat16(x);
    __nv_bfloat16 hy = __float2bfloat16(y);
    float fx = __bfloat162float(hx), fy = __bfloat162float(hy);
    __nv_bfloat16 lx = __float2bfloat16(x - fx);
    __nv_bfloat16 ly = __float2bfloat16(y - fy);
    uint16_t uhx = *(uint16_t*)&hx, uhy = *(uint16_t*)&hy;
    uint16_t ulx = *(uint16_t*)&lx, uly = *(uint16_t*)&ly;
    hi = ((uint32_t)uhy << 16) | uhx;
    lo = ((uint32_t)uly << 16) | ulx;
}

// ---------------------------------------------------------------------------
// generic fp32 -> bf16 hi/lo split (n4 float4 elements)
// ---------------------------------------------------------------------------
__global__ void __launch_bounds__(256) split_kernel(
    const float* __restrict__ in,
    __nv_bfloat16* __restrict__ oh, __nv_bfloat16* __restrict__ ol, int n4)
{
    int i = blockIdx.x * blockDim.x + threadIdx.x;
    if (i >= n4) return;
    float4 v = ((const float4*)in)[i];
    uint32_t h01, l01, h23, l23;
    split2(v.x, v.y, h01, l01);
    split2(v.z, v.w, h23, l23);
    *(uint2*)(oh + (size_t)i * 4) = make_uint2(h01, h23);
    *(uint2*)(ol + (size_t)i * 4) = make_uint2(l01, l23);
}

// ---------------------------------------------------------------------------
// bf16x3 warp-MMA GEMM, bf16 hi/lo inputs, cp.async 3-stage pipeline.
// C[M,N] = A*B^T (+ cross terms).  CTA 128x128, BK=32, 8 warps 64x32.
// Stage (32KB): Ah 8K | Al 8K | Bh 8K | Bl 8K. Swizzle: chunk c ^ ((r>>1)&3).
// ---------------------------------------------------------------------------
#define GSTG 32768

__global__ void __launch_bounds__(256, 2) mma_gemm_bf16_nt(
    const __nv_bfloat16* __restrict__ Ah, const __nv_bfloat16* __restrict__ Al,
    const __nv_bfloat16* __restrict__ Bh, const __nv_bfloat16* __restrict__ Bl,
    float* __restrict__ C, int M, int N, int K)
{
    extern __shared__ char smc[];
    const uint32_t smb = smem_u32(smc);
    const int tid  = threadIdx.x;
    const int lane = tid & 31;
    const int wid  = tid >> 5;
    const int m0w  = (wid >> 2) * 64;
    const int n0w  = (wid & 3) * 32;

    const size_t brow = (size_t)blockIdx.y * 128;
    const size_t bcol = (size_t)blockIdx.x * 128;
    const __nv_bfloat16* Ahg = Ah + brow * K;
    const __nv_bfloat16* Alg = Al + brow * K;
    const __nv_bfloat16* Bhg = Bh + bcol * K;
    const __nv_bfloat16* Blg = Bl + bcol * K;

    // issue one stage: 2048 x 16B chunks, 8 per thread (arr index compile-time)
    auto issue_stage = [&](int slot, int k0) {
        const uint32_t sb = smb + (uint32_t)slot * GSTG;
        #pragma unroll
        for (int i = 0; i < 8; i++) {
            const __nv_bfloat16* gp = (i < 2) ? Ahg : (i < 4) ? Alg
                                    : (i < 6) ? Bhg : Blg;
            int idx = tid + (i & 1) * 256;       // 0..511
            int r = idx >> 2, c = idx & 3;
            uint32_t dst = sb + (uint32_t)(i >> 1) * 8192
                         + (uint32_t)r * 64 + (uint32_t)((c ^ ((r >> 1) & 3)) << 4);
            cp16(dst, gp + (size_t)r * K + k0 + c * 8);
        }
        cp_commit();
    };

    float acc[4][4][4];
    #pragma unroll
    for (int mt = 0; mt < 4; mt++)
        #pragma unroll
        for (int nt = 0; nt < 4; nt++)
            #pragma unroll
            for (int q = 0; q < 4; q++) acc[mt][nt][q] = 0.0f;

    // prologue: 3 stages in flight
    issue_stage(0, 0);
    issue_stage(1, 32);
    issue_stage(2, 64);

    const int NKB = K >> 5;
    int slot = 0;
    for (int kb = 0; kb < NKB; kb++) {
        cp_wait<2>();
        __syncthreads();

        const uint32_t base = smb + (uint32_t)slot * GSTG;
        #pragma unroll
        for (int ks = 0; ks < 2; ks++) {
            uint32_t Ahi[4][4], Alo[4][4];
            #pragma unroll
            for (int mt = 0; mt < 4; mt++) {
                int r  = m0w + mt * 16 + (lane & 15);
                int ch = 2 * ks + (lane >> 4);
                uint32_t off = (uint32_t)r * 64 + (uint32_t)((ch ^ ((r >> 1) & 3)) << 4);
                ldsm_x4(Ahi[mt], base + off);
                ldsm_x4(Alo[mt], base + 8192 + off);
            }
            #pragma unroll
            for (int nt = 0; nt < 4; nt++) {
                int r  = n0w + nt * 8 + (lane & 7);
                int ch = 2 * ks + ((lane >> 3) & 1);
                uint32_t off = (uint32_t)r * 64 + (uint32_t)((ch ^ ((r >> 1) & 3)) << 4);
                uint32_t Bhi[2], Blo[2];
                ldsm_x2(Bhi, base + 16384 + off);
                ldsm_x2(Blo, base + 24576 + off);
                #pragma unroll
                for (int mt = 0; mt < 4; mt++) {
                    mma16816(acc[mt][nt], Ahi[mt], Bhi);
                    mma16816(acc[mt][nt], Ahi[mt], Blo);
                    mma16816(acc[mt][nt], Alo[mt], Bhi);
                }
            }
        }
        __syncthreads();
        if (kb + 3 < NKB) issue_stage(slot, (kb + 3) << 5);
        slot = (slot == 2) ? 0 : slot + 1;
    }

    #pragma unroll
    for (int mt = 0; mt < 4; mt++) {
        int row0 = m0w + mt * 16 + (lane >> 2);
        #pragma unroll
        for (int nt = 0; nt < 4; nt++) {
            int col = n0w + nt * 8 + (lane & 3) * 2;
            float* p = C + (brow + row0) * N + bcol + col;
            *(float2*)p           = make_float2(acc[mt][nt][0], acc[mt][nt][1]);
            *(float2*)(p + 8 * N) = make_float2(acc[mt][nt][2], acc[mt][nt][3]);
        }
    }
}

// ---------------------------------------------------------------------------
// RMSNorm + RoPE on q,k  ->  bf16 hi/lo arrays
// ---------------------------------------------------------------------------
__global__ void __launch_bounds__(256) rmsrope_split_kernel(
    const float* __restrict__ qkv,
    __nv_bfloat16* __restrict__ qh, __nv_bfloat16* __restrict__ ql)
{
    int gv   = (blockIdx.x * blockDim.x + threadIdx.x) >> 5;
    int lane = threadIdx.x & 31;
    int which = gv & 1;
    int h     = (gv >> 1) & 15;
    int m     = gv >> 5;
    int t     = m & (T_ - 1);

    size_t off = (size_t)m * (3 * C_) + which * C_ + h * HD_;
    const float* base = qkv + off;
    float x1 = base[lane];
    float x2 = base[lane + 32];

    float ss = x1 * x1 + x2 * x2;
    #pragma unroll
    for (int o = 16; o; o >>= 1)
        ss += __shfl_xor_sync(0xffffffffu, ss, o);
    float r = rsqrtf(ss * (1.0f / 64.0f) + 1.1920929e-07f);
    x1 *= r; x2 *= r;

    float inv_f = powf(10000.0f, -(float)lane * (1.0f / 32.0f));
    float ang   = (float)t * inv_f;
    float cf, sf;
    sincosf(ang, &sf, &cf);
    float c = __bfloat162float(__float2bfloat16(cf));
    float s = __bfloat162float(__float2bfloat16(sf));

    float y1 =  x1 * c + x2 * s;
    float y2 = -x1 * s + x2 * c;

    __nv_bfloat16 h1 = __float2bfloat16(y1);
    __nv_bfloat16 h2 = __float2bfloat16(y2);
    qh[off + lane]      = h1;
    qh[off + lane + 32] = h2;
    ql[off + lane]      = __float2bfloat16(y1 - __bfloat162float(h1));
    ql[off + lane + 32] = __float2bfloat16(y2 - __bfloat162float(h2));
}

// ---------------------------------------------------------------------------
// V: elementwise fp32 -> bf16 hi/lo
// ---------------------------------------------------------------------------
__global__ void __launch_bounds__(256) vsplit_kernel(
    const float* __restrict__ qkv,
    __nv_bfloat16* __restrict__ qh, __nv_bfloat16* __restrict__ ql)
{
    int idx = blockIdx.x * blockDim.x + threadIdx.x;
    int m   = idx >> 8;
    int dq  = (idx & 255) << 2;
    size_t off = (size_t)m * (3 * C_) + 2 * C_ + dq;
    float4 v = *(const float4*)(qkv + off);
    uint32_t h01, l01, h23, l23;
    split2(v.x, v.y, h01, l01);
    split2(v.z, v.w, h23, l23);
    *(uint2*)(qh + off) = make_uint2(h01, h23);
    *(uint2*)(ql + off) = make_uint2(l01, l23);
}

// ---------------------------------------------------------------------------
// Flash attention, bf16x3 warp MMA, cp.async double-buffered K/V.
// Smem: Q 32K  |  KV stage0 32K  |  KV stage1 32K   (98304 B)
// KV stage: Khi 8K | Klo 8K | Vhi 8K | Vlo 8K, swizzle chunk c ^ (r&7).
// Output written directly as bf16 hi/lo (feeds proj GEMM).
// ---------------------------------------------------------------------------
#define FQ_HI 0
#define FQ_LO 16384
#define FKV0  32768

__global__ void __launch_bounds__(256) flash_mma_kernel(
    const __nv_bfloat16* __restrict__ qh, const __nv_bfloat16* __restrict__ ql,
    __nv_bfloat16* __restrict__ yh, __nv_bfloat16* __restrict__ yl)
{
    extern __shared__ char smc[];
    const uint32_t smb = smem_u32(smc);
    const int tid  = threadIdx.x;
    const int lane = tid & 31;
    const int wid  = tid >> 5;
    const int qblk = blockIdx.x;
    const int bh   = blockIdx.y;
    const int b    = bh >> 4, h = bh & 15;
    const int q0   = qblk * 128;

    const size_t hb = (size_t)b * T_ * (3 * C_) + h * HD_;

    auto issue_kv = [&](int buf, int k0) {
        const uint32_t sb = smb + FKV0 + (uint32_t)buf * 32768;
        #pragma unroll
        for (int i = 0; i < 8; i++) {
            int idx = tid + (i & 1) * 256;      // 0..511
            int r = idx >> 3, c = idx & 7;
            size_t go = hb + (size_t)(k0 + r) * (3 * C_) + c * 8;
            const __nv_bfloat16* gp =
                (i < 2) ? (qh + go + C_)     : (i < 4) ? (ql + go + C_)
              : (i < 6) ? (qh + go + 2 * C_) : (ql + go + 2 * C_);
            uint32_t dst = sb + (uint32_t)(i >> 1) * 8192
                         + (uint32_t)r * 128 + (uint32_t)((c ^ (r & 7)) << 4);
            cp16(dst, gp);
        }
        cp_commit();
    };

    // Q tile copy (plain loads, once)
    #pragma unroll
    for (int i = 0; i < 4; i++) {
        int t = tid + i * 256;
        int r = t >> 3, c = t & 7;
        size_t go = hb + (size_t)(q0 + r) * (3 * C_) + c * 8;
        uint4 hv = *(const uint4*)(qh + go);
        uint4 lv = *(const uint4*)(ql + go);
        uint32_t off = r * 128 + ((c ^ (r & 7)) << 4);
        *(uint4*)(smc + FQ_HI + off) = hv;
        *(uint4*)(smc + FQ_LO + off) = lv;
    }
    issue_kv(0, 0);
    __syncthreads();

    // per-warp Q A-fragments
    uint32_t Qh[4][4], Ql[4][4];
    {
        int r = wid * 16 + (lane & 15);
        #pragma unroll
        for (int s = 0; s < 4; s++) {
            int ch = 2 * s + (lane >> 4);
            uint32_t off = r * 128 + ((ch ^ (r & 7)) << 4);
            ldsm_x4(Qh[s], smb + FQ_HI + off);
            ldsm_x4(Ql[s], smb + FQ_LO + off);
        }
    }

    float S[8][4], O[8][4];
    float rmax[2] = {-1e30f, -1e30f}, rsum[2] = {0.f, 0.f};
    #pragma unroll
    for (int j = 0; j < 8; j++)
        #pragma unroll
        for (int q = 0; q < 4; q++) O[j][q] = 0.f;

    const int row0 = q0 + wid * 16 + (lane >> 2);
    const int ktiles = 2 * qblk + 2;

    for (int kt = 0; kt < ktiles; kt++) {
        const int k0 = kt * 64;
        if (kt + 1 < ktiles) {
            issue_kv((kt + 1) & 1, k0 + 64);
            cp_wait<1>();
        } else {
            cp_wait<0>();
        }
        __syncthreads();
        const uint32_t kvb = smb + FKV0 + (uint32_t)(kt & 1) * 32768;

        // S = Q K^T (3-term bf16)
        #pragma unroll
        for (int j = 0; j < 8; j++)
            #pragma unroll
            for (int q = 0; q < 4; q++) S[j][q] = 0.f;

        #pragma unroll
        for (int jp = 0; jp < 4; jp++) {
            #pragma unroll
            for (int s = 0; s < 4; s++) {
                int r  = jp * 16 + (lane & 15);
                int ch = 2 * s + (lane >> 4);
                uint32_t off = r * 128 + ((ch ^ (r & 7)) << 4);
                uint32_t Bh[4], Bl[4];
                ldsm_x4(Bh, kvb + off);
                ldsm_x4(Bl, kvb + 8192 + off);
                uint32_t b0h[2] = {Bh[0], Bh[2]}, b1h[2] = {Bh[1], Bh[3]};
                uint32_t b0l[2] = {Bl[0], Bl[2]}, b1l[2] = {Bl[1], Bl[3]};
                mma16816(S[2*jp],   Qh[s], b0h);
                mma16816(S[2*jp],   Ql[s], b0h);
                mma16816(S[2*jp],   Qh[s], b0l);
                mma16816(S[2*jp+1], Qh[s], b1h);
                mma16816(S[2*jp+1], Ql[s], b1h);
                mma16816(S[2*jp+1], Qh[s], b1l);
            }
        }

        // scale + causal mask
        if (kt >= 2 * qblk) {
            #pragma unroll
            for (int j = 0; j < 8; j++) {
                int colb = k0 + j * 8 + (lane & 3) * 2;
                #pragma unroll
                for (int q = 0; q < 4; q++) {
                    int key  = colb + (q & 1);
                    int grow = row0 + (q >> 1) * 8;
                    S[j][q] = (key > grow) ? -1e30f : S[j][q] * 0.125f;
                }
            }
        } else {
            #pragma unroll
            for (int j = 0; j < 8; j++)
                #pragma unroll
                for (int q = 0; q < 4; q++) S[j][q] *= 0.125f;
        }

        // online softmax
        #pragma unroll
        for (int hf = 0; hf < 2; hf++) {
            float mx = -1e30f;
            #pragma unroll
            for (int j = 0; j < 8; j++)
                mx = fmaxf(mx, fmaxf(S[j][2*hf], S[j][2*hf+1]));
            mx = fmaxf(mx, __shfl_xor_sync(0xffffffffu, mx, 1));
            mx = fmaxf(mx, __shfl_xor_sync(0xffffffffu, mx, 2));
            float nm   = fmaxf(rmax[hf], mx);
            float corr = __expf(rmax[hf] - nm);
            rmax[hf] = nm;
            float ps = 0.f;
            #pragma unroll
            for (int j = 0; j < 8; j++) {
                float e0 = __expf(S[j][2*hf]   - nm);
                float e1 = __expf(S[j][2*hf+1] - nm);
                S[j][2*hf] = e0; S[j][2*hf+1] = e1;
                ps += e0 + e1;
            }
            ps += __shfl_xor_sync(0xffffffffu, ps, 1);
            ps += __shfl_xor_sync(0xffffffffu, ps, 2);
            rsum[hf] = rsum[hf] * corr + ps;
            #pragma unroll
            for (int j = 0; j < 8; j++) { O[j][2*hf] *= corr; O[j][2*hf+1] *= corr; }
        }

        // O += P V
        #pragma unroll
        for (int s = 0; s < 4; s++) {
            uint32_t Ph[4], Pl[4];
            split2(S[2*s][0],   S[2*s][1],   Ph[0], Pl[0]);
            split2(S[2*s][2],   S[2*s][3],   Ph[1], Pl[1]);
            split2(S[2*s+1][0], S[2*s+1][1], Ph[2], Pl[2]);
            split2(S[2*s+1][2], S[2*s+1][3], Ph[3], Pl[3]);
            #pragma unroll
            for (int jp = 0; jp < 4; jp++) {
                int mm = lane >> 3, lr = lane & 7;
                int r  = 16 * s + lr + 8 * (mm & 1);
                int ch = 2 * jp + (mm >> 1);
                uint32_t off = r * 128 + ((ch ^ (r & 7)) << 4);
                uint32_t Bh[4], Bl[4];
                ldsm_x4_t(Bh, kvb + 16384 + off);
                ldsm_x4_t(Bl, kvb + 24576 + off);
                uint32_t b0h[2] = {Bh[0], Bh[1]}, b1h[2] = {Bh[2], Bh[3]};
                uint32_t b0l[2] = {Bl[0], Bl[1]}, b1l[2] = {Bl[2], Bl[3]};
                mma16816(O[2*jp],   Ph, b0h);
                mma16816(O[2*jp],   Pl, b0h);
                mma16816(O[2*jp],   Ph, b0l);
                mma16816(O[2*jp+1], Ph, b1h);
                mma16816(O[2*jp+1], Pl, b1h);
                mma16816(O[2*jp+1], Ph, b1l);
            }
        }
        __syncthreads();
    }

    // epilogue: write bf16 hi/lo y
    float inv0 = 1.f / rsum[0], inv1 = 1.f / rsum[1];
    #pragma unroll
    for (int j = 0; j < 8; j++) {
        int col = h * HD_ + j * 8 + (lane & 3) * 2;
        size_t base0 = ((size_t)b * T_ + row0) * C_ + col;
        uint32_t h01, l01, h23, l23;
        split2(O[j][0] * inv0, O[j][1] * inv0, h01, l01);
        split2(O[j][2] * inv1, O[j][3] * inv1, h23, l23);
        *(uint32_t*)(yh + base0) = h01;
        *(uint32_t*)(yl + base0) = l01;
        *(uint32_t*)(yh + base0 + 8 * (size_t)C_) = h23;
        *(uint32_t*)(yl + base0 + 8 * (size_t)C_) = l23;
    }
}

// ---------------------------------------------------------------------------
// Launch
// ---------------------------------------------------------------------------
extern "C" void kernel_launch(void* const* d_in, const int* in_sizes, int n_in,
                              void* d_out, int out_size)
{
    const float* x      = (const float*)d_in[0];
    const float* w_attn = (const float*)d_in[1];
    const float* w_proj = (const float*)d_in[2];
    float* out = (float*)d_out;

    float* qkv = nullptr;
    __nv_bfloat16 *qkvh, *qkvl, *xh, *xl, *wah, *wal, *wph, *wpl, *yh, *yl;
    cudaGetSymbolAddress((void**)&qkv,  g_qkv);
    cudaGetSymbolAddress((void**)&qkvh, g_qkvh);
    cudaGetSymbolAddress((void**)&qkvl, g_qkvl);
    cudaGetSymbolAddress((void**)&xh,   g_xh);
    cudaGetSymbolAddress((void**)&xl,   g_xl);
    cudaGetSymbolAddress((void**)&wah,  g_wah);
    cudaGetSymbolAddress((void**)&wal,  g_wal);
    cudaGetSymbolAddress((void**)&wph,  g_wph);
    cudaGetSymbolAddress((void**)&wpl,  g_wpl);
    cudaGetSymbolAddress((void**)&yh,   g_yh);
    cudaGetSymbolAddress((void**)&yl,   g_yl);

    const int gemm_smem  = 3 * GSTG;        // 98304
    const int flash_smem = 32768 + 2 * 32768; // 98304
    cudaFuncSetAttribute(mma_gemm_bf16_nt,
                         cudaFuncAttributeMaxDynamicSharedMemorySize, gemm_smem);
    cudaFuncSetAttribute(flash_mma_kernel,
                         cudaFuncAttributeMaxDynamicSharedMemorySize, flash_smem);

    // 0) split inputs to bf16 hi/lo
    split_kernel<<<(M_ * C_ / 4) / 256, 256>>>(x, xh, xl, M_ * C_ / 4);
    split_kernel<<<(3 * C_ * C_ / 4) / 256, 256>>>(w_attn, wah, wal, 3 * C_ * C_ / 4);
    split_kernel<<<(C_ * C_ / 4) / 256, 256>>>(w_proj, wph, wpl, C_ * C_ / 4);

    // 1) qkv = x @ w_attn^T
    {
        dim3 grid(3 * C_ / 128, M_ / 128);
        mma_gemm_bf16_nt<<<grid, 256, gemm_smem>>>(xh, xl, wah, wal, qkv,
                                                   M_, 3 * C_, C_);
    }

    // 2) RMSNorm + RoPE on q,k -> bf16 hi/lo ; V -> bf16 hi/lo
    rmsrope_split_kernel<<<(2 * M_ * H_) / 8, 256>>>(qkv, qkvh, qkvl);
    vsplit_kernel<<<(M_ * C_ / 4) / 256, 256>>>(qkv, qkvh, qkvl);

    // 3) Flash attention -> yh/yl
    {
        dim3 grid(T_ / 128, B_ * H_);
        flash_mma_kernel<<<grid, 256, flash_smem>>>(qkvh, qkvl, yh, yl);
    }

    // 4) out = y @ w_proj^T
    {
        dim3 grid(C_ / 128, M_ / 128);
        mma_gemm_bf16_nt<<<grid, 256, gemm_smem>>>(yh, yl, wph, wpl, out,
                                                   M_, C_, C_);
    }
}